// round 5
// baseline (speedup 1.0000x reference)
#include <cuda_runtime.h>
#include <cuda_bf16.h>
#include <stdint.h>
#include <math.h>

#define B_    64
#define I_    48
#define O_    48
#define F_    256
#define H_    256
#define FIVEH 1280
#define KST   512
#define PRE_ROWS 3072
#define STAGE 55296              // A: 128*144 + B: 256*144
#define ASIZE 18432
#define SMEM_TOTAL (2 * STAGE)   // 110592
#define NCTA  148

// ---------------- scratch (device globals) ----------------------------------
__device__ float g_PX[I_ * B_ * FIVEH];
__device__ float g_PY[O_ * B_ * FIVEH];
__device__ __nv_bfloat16 g_WT_hi[FIVEH * KST];
__device__ __nv_bfloat16 g_WT_lo[FIVEH * KST];
__device__ __nv_bfloat16 g_Shi[2][I_ * B_ * H_];
__device__ __nv_bfloat16 g_Slo[2][I_ * B_ * H_];
__device__ float g_C[2][I_ * B_ * H_];
__device__ float g_PRE[3][PRE_ROWS * FIVEH];
__device__ unsigned g_count;
__device__ unsigned g_epoch;

__device__ __forceinline__ float sigf(float x) { return 1.0f / (1.0f + expf(-x)); }

__device__ __forceinline__ uint32_t smem_u32(const void* p) {
    uint32_t a;
    asm("{ .reg .u64 t; cvta.to.shared.u64 t, %1; cvt.u32.u64 %0, t; }" : "=r"(a) : "l"(p));
    return a;
}
__device__ __forceinline__ void cp16(uint32_t dst, const void* src, bool v) {
    int sz = v ? 16 : 0;
    asm volatile("cp.async.cg.shared.global [%0], [%1], 16, %2;"
                 :: "r"(dst), "l"(src), "r"(sz) : "memory");
}
#define CP_COMMIT() asm volatile("cp.async.commit_group;" ::: "memory")
#define CP_WAIT(n)  asm volatile("cp.async.wait_group %0;" :: "n"(n) : "memory")

__device__ __forceinline__ void ldmA(uint32_t* a, uint32_t addr) {
    asm volatile("ldmatrix.sync.aligned.m8n8.x4.shared.b16 {%0,%1,%2,%3}, [%4];"
                 : "=r"(a[0]), "=r"(a[1]), "=r"(a[2]), "=r"(a[3]) : "r"(addr));
}
__device__ __forceinline__ void ldmB(uint32_t* b, uint32_t addr) {
    asm volatile("ldmatrix.sync.aligned.m8n8.x2.shared.b16 {%0,%1}, [%2];"
                 : "=r"(b[0]), "=r"(b[1]) : "r"(addr));
}
__device__ __forceinline__ void mma16816(float* c, const uint32_t* a, const uint32_t* b) {
    asm volatile("mma.sync.aligned.m16n8k16.row.col.f32.bf16.bf16.f32 "
                 "{%0,%1,%2,%3}, {%4,%5,%6,%7}, {%8,%9}, {%0,%1,%2,%3};"
                 : "+f"(c[0]), "+f"(c[1]), "+f"(c[2]), "+f"(c[3])
                 : "r"(a[0]), "r"(a[1]), "r"(a[2]), "r"(a[3]), "r"(b[0]), "r"(b[1]));
}

// ---------------- grid barrier (sense via monotonic epoch) -------------------
__device__ __forceinline__ unsigned ld_epoch() {
    unsigned e;
    asm volatile("ld.acquire.gpu.global.u32 %0, [%1];" : "=r"(e) : "l"(&g_epoch));
    return e;
}
__device__ __forceinline__ void grid_barrier(unsigned target) {
    __threadfence();
    __syncthreads();
    if (threadIdx.x == 0) {
        unsigned old;
        asm volatile("atom.add.release.gpu.global.u32 %0, [%1], 1;"
                     : "=r"(old) : "l"(&g_count) : "memory");
        if (old == NCTA - 1) {
            g_count = 0;  // safe: all arrived; published by release below
            asm volatile("red.release.gpu.global.add.u32 [%0], 1;"
                         :: "l"(&g_epoch) : "memory");
        } else {
            while ((int)(ld_epoch() - target) < 0) { }
        }
    }
    __syncthreads();
}

// ---------------------------------------------------------------------------
// Setup kernels
// ---------------------------------------------------------------------------
__global__ __launch_bounds__(256) void split_ws_kernel(const float* __restrict__ Ws) {
    int idx = blockIdx.x * 256 + threadIdx.x;
    if (idx >= FIVEH * KST) return;
    int n = idx / KST, k = idx % KST;
    float w = Ws[k * FIVEH + n];
    __nv_bfloat16 hi = __float2bfloat16(w);
    g_WT_hi[idx] = hi;
    g_WT_lo[idx] = __float2bfloat16(w - __bfloat162float(hi));
}

__global__ __launch_bounds__(256) void precompute_kernel(
    const float* __restrict__ x, const float* __restrict__ y,
    const float* __restrict__ Wx)
{
    const int cell = blockIdx.x, n0 = blockIdx.y * 128, which = blockIdx.z;
    const float* A = which ? y : x;
    const int koff = which ? F_ : 0;
    float* P = which ? g_PY : g_PX;

    __shared__ float As[16][68];
    __shared__ float Bs[16][128];
    const int t = threadIdx.x;
    const int tx = t & 15, ty = t >> 4;
    const int lm = t >> 2, lk = (t & 3) * 4;

    float acc[4][8];
#pragma unroll
    for (int r = 0; r < 4; r++)
#pragma unroll
        for (int q = 0; q < 8; q++) acc[r][q] = 0.f;

    for (int k0 = 0; k0 < F_; k0 += 16) {
        float4 av = *(const float4*)&A[(lm * I_ + cell) * F_ + k0 + lk];
        As[lk + 0][lm] = av.x; As[lk + 1][lm] = av.y;
        As[lk + 2][lm] = av.z; As[lk + 3][lm] = av.w;
#pragma unroll
        for (int s = 0; s < 2; s++) {
            int idx = t + 256 * s;
            int kl = idx >> 5, c4 = idx & 31;
            *(float4*)&Bs[kl][c4 * 4] =
                *(const float4*)&Wx[(koff + k0 + kl) * FIVEH + n0 + c4 * 4];
        }
        __syncthreads();
#pragma unroll
        for (int k = 0; k < 16; k++) {
            float4 a4 = *(const float4*)&As[k][ty * 4];
            float4 b0 = *(const float4*)&Bs[k][tx * 8];
            float4 b1 = *(const float4*)&Bs[k][tx * 8 + 4];
            float a[4] = {a4.x, a4.y, a4.z, a4.w};
            float bb[8] = {b0.x, b0.y, b0.z, b0.w, b1.x, b1.y, b1.z, b1.w};
#pragma unroll
            for (int r = 0; r < 4; r++)
#pragma unroll
                for (int q = 0; q < 8; q++) acc[r][q] += a[r] * bb[q];
        }
        __syncthreads();
    }
#pragma unroll
    for (int r = 0; r < 4; r++) {
        int m = ty * 4 + r;
        float* dst = &P[(cell * B_ + m) * FIVEH + n0 + tx * 8];
        *(float4*)dst       = make_float4(acc[r][0], acc[r][1], acc[r][2], acc[r][3]);
        *(float4*)(dst + 4) = make_float4(acc[r][4], acc[r][5], acc[r][6], acc[r][7]);
    }
}

// ---------------------------------------------------------------------------
// One GEMM tile task (M=128, N=256, K=512) — R4 body
// ---------------------------------------------------------------------------
__device__ __forceinline__ void gemm_tile(
    char* smem, uint32_t sb, int d, int i_lo, int i_hi,
    int mtile, int ny, int term)
{
    const int t = threadIdx.x;
    const int i0 = i_lo + 2 * mtile;
    const int prv = (d & 1) ^ 1;

    const __nv_bfloat16* __restrict__ Ssrc = (term == 1) ? g_Slo[prv] : g_Shi[prv];
    const __nv_bfloat16* __restrict__ Wsrc = (term == 2) ? g_WT_lo : g_WT_hi;

    __syncthreads();   // protect smem reuse across tasks

    auto load_chunk = [&](int c8, int buf) {
        const bool hor = (c8 < 4);
        const int kc = (c8 & 3) * 64;
        const int kr = c8 * 64;
        const uint32_t base = sb + buf * STAGE;
#pragma unroll
        for (int p = 0; p < 4; p++) {
            int idx = t + 256 * p;
            int row = idx >> 3, seg = idx & 7;
            int cell = i0 + (row >> 6);
            int b = row & 63;
            bool cv = (cell <= i_hi);
            bool valid; int scell;
            if (hor) { valid = cv && (cell > 0); scell = cell - 1; }
            else     { valid = cv && (d - cell > 0); scell = cell; }
            const __nv_bfloat16* g = valid ?
                (Ssrc + ((scell * B_) + b) * H_ + kc + seg * 8) : Ssrc;
            cp16(base + row * 144 + seg * 16, g, valid);
        }
#pragma unroll
        for (int p = 0; p < 8; p++) {
            int idx = t + 256 * p;
            int rr = idx >> 3, seg = idx & 7;
            const __nv_bfloat16* g = Wsrc + (ny * 256 + rr) * KST + kr + seg * 8;
            cp16(base + ASIZE + rr * 144 + seg * 16, g, true);
        }
    };

    const int wid = t >> 5, lane = t & 31;
    const int wm = wid >> 2, wn = wid & 3;
    const int m0 = wm * 64, n0 = wn * 64;

    const uint32_t aoff = (uint32_t)((m0 + ((lane >> 3) & 1) * 8 + (lane & 7)) * 144
                                     + (lane >> 4) * 16);
    const uint32_t boff = (uint32_t)(ASIZE + (n0 + (lane & 7)) * 144
                                     + ((lane >> 3) & 1) * 16);

    float acc[4][8][4];
#pragma unroll
    for (int f = 0; f < 4; f++)
#pragma unroll
        for (int e = 0; e < 8; e++)
#pragma unroll
            for (int q = 0; q < 4; q++) acc[f][e][q] = 0.f;

    load_chunk(0, 0);
    CP_COMMIT();

    for (int c8 = 0; c8 < 8; c8++) {
        if (c8 < 7) {
            load_chunk(c8 + 1, (c8 + 1) & 1);
            CP_COMMIT();
            CP_WAIT(1);
        } else {
            CP_WAIT(0);
        }
        __syncthreads();

        const uint32_t bufb = sb + (c8 & 1) * STAGE;
#pragma unroll
        for (int ks = 0; ks < 4; ks++) {
            uint32_t afr[4][4];
#pragma unroll
            for (int f = 0; f < 4; f++)
                ldmA(afr[f], bufb + aoff + f * 2304 + ks * 32);
            uint32_t bfr[8][2];
#pragma unroll
            for (int e = 0; e < 8; e++)
                ldmB(bfr[e], bufb + boff + e * 1152 + ks * 32);
#pragma unroll
            for (int f = 0; f < 4; f++)
#pragma unroll
                for (int e = 0; e < 8; e++)
                    mma16816(acc[f][e], afr[f], bfr[e]);
        }
        if (c8 < 7) __syncthreads();
    }

    float* __restrict__ PRE = g_PRE[term];
    const int rbase = mtile * 128 + m0 + (lane >> 2);
    const int cbase = ny * 256 + n0 + (lane & 3) * 2;
#pragma unroll
    for (int f = 0; f < 4; f++) {
#pragma unroll
        for (int e = 0; e < 8; e++) {
            const int r0 = rbase + 16 * f;
            const int cc = cbase + 8 * e;
            *(float2*)&PRE[(size_t)r0 * FIVEH + cc]       = make_float2(acc[f][e][0], acc[f][e][1]);
            *(float2*)&PRE[(size_t)(r0 + 8) * FIVEH + cc] = make_float2(acc[f][e][2], acc[f][e][3]);
        }
    }
}

// ---------------------------------------------------------------------------
// Pointwise for one (cell,b) row; 256 threads map h
// ---------------------------------------------------------------------------
__device__ __forceinline__ void point_row(
    const float* __restrict__ bias, float* __restrict__ out,
    int d, int i_lo, int row)
{
    const int q = row >> 6, b = row & 63;
    const int i = i_lo + q;
    const int j = d - i;
    const int h = threadIdx.x;
    const int cur = d & 1, prv = cur ^ 1;
    const bool hh = (i > 0), vv = (j > 0);

    const float* __restrict__ Cp = g_C[prv];
    float* __restrict__ Cc = g_C[cur];
    __nv_bfloat16* __restrict__ Shc = g_Shi[cur];
    __nv_bfloat16* __restrict__ Slc = g_Slo[cur];

    const size_t pos = (size_t)row * FIVEH;
    const size_t pxo = ((size_t)i * B_ + b) * FIVEH;
    const size_t pyo = ((size_t)j * B_ + b) * FIVEH;

    float pre[5];
#pragma unroll
    for (int g = 0; g < 5; g++) {
        const int col = g * H_ + h;
        pre[g] = g_PRE[0][pos + col] + g_PRE[1][pos + col] + g_PRE[2][pos + col]
               + g_PX[pxo + col] + g_PY[pyo + col] + bias[col];
    }
    float ch = hh ? Cp[(((i - 1) * B_) + b) * H_ + h] : 0.f;
    float cv = vv ? Cp[((i * B_) + b) * H_ + h] : 0.f;

    float ig = sigf(pre[0]);
    float fg = sigf(pre[1]);
    float og = sigf(pre[2]);
    float lg = sigf(pre[3]);
    float gg = tanhf(pre[4]);
    float c = fg * (lg * ch + (1.f - lg) * cv) + ig * gg;
    float s = og * tanhf(c);

    const size_t sidx = ((size_t)i * B_ + b) * H_ + h;
    Cc[sidx] = c;
    __nv_bfloat16 shi = __float2bfloat16(s);
    Shc[sidx] = shi;
    Slc[sidx] = __float2bfloat16(s - __bfloat162float(shi));
    out[(((size_t)i * O_ + j) * B_ + b) * H_ + h] = s;
}

// ---------------------------------------------------------------------------
// Persistent kernel: all 95 diagonals, grid barriers between phases
// ---------------------------------------------------------------------------
__global__ __launch_bounds__(256, 1) void persist_kernel(
    const float* __restrict__ bias, float* __restrict__ out)
{
    extern __shared__ char smem[];
    const uint32_t sb = smem_u32(smem);

    const unsigned epoch0 = ld_epoch();
    unsigned bars = 0;

    for (int d = 0; d < I_ + O_ - 1; d++) {
        const int i_lo = (d > O_ - 1) ? d - (O_ - 1) : 0;
        const int i_hi = (d < I_ - 1) ? d : I_ - 1;
        const int nv = i_hi - i_lo + 1;
        const int mt = (nv + 1) >> 1;

        // Phase A: GEMM tile tasks
        const int ntasks = mt * 15;
        for (int task = blockIdx.x; task < ntasks; task += NCTA) {
            const int mtile = task / 15;
            const int rem = task - mtile * 15;
            gemm_tile(smem, sb, d, i_lo, i_hi, mtile, rem / 3, rem % 3);
        }
        bars++; grid_barrier(epoch0 + bars);

        // Phase B: pointwise rows
        const int rows = nv * 64;
        for (int row = blockIdx.x; row < rows; row += NCTA)
            point_row(bias, out, d, i_lo, row);
        bars++; grid_barrier(epoch0 + bars);
    }
}

// ---------------------------------------------------------------------------
extern "C" void kernel_launch(void* const* d_in, const int* in_sizes, int n_in,
                              void* d_out, int out_size)
{
    const float* x  = (const float*)d_in[0];
    const float* y  = (const float*)d_in[1];
    const float* Wx = (const float*)d_in[2];
    const float* Ws = (const float*)d_in[3];
    const float* b  = (const float*)d_in[4];
    float* out = (float*)d_out;

    cudaFuncSetAttribute(persist_kernel, cudaFuncAttributeMaxDynamicSharedMemorySize,
                         SMEM_TOTAL);

    split_ws_kernel<<<(FIVEH * KST + 255) / 256, 256>>>(Ws);
    precompute_kernel<<<dim3(I_, FIVEH / 128, 2), 256>>>(x, y, Wx);
    persist_kernel<<<NCTA, 256, SMEM_TOTAL>>>(b, out);
}

// round 6
// speedup vs baseline: 1.5110x; 1.5110x over previous
#include <cuda_runtime.h>
#include <cuda_fp16.h>
#include <stdint.h>
#include <math.h>

#define B_    64
#define I_    48
#define O_    48
#define F_    256
#define H_    256
#define FIVEH 1280
#define NCTA  148

// smem layout (per stage): B tile 160x64(fp16) rows stride 144B, then A hi/lo
#define BBYTES 23040                  // 160*144
#define APASS  9216                   // 64*144
#define STAGE  (BBYTES + 2*APASS)     // 41472
#define SMEM_TOTAL (2*STAGE)          // 82944  (epilogue reuses: 64*160*4=40960)

// ---------------- scratch (device globals) ----------------------------------
__device__ float g_PX[I_ * B_ * FIVEH];          // gate-major: [i][b][g*256+h]
__device__ float g_PY[O_ * B_ * FIVEH];
__device__ __half g_Wh[FIVEH * 512];             // W' fp16, [n'][k], n'=h*5+g
__device__ __half g_Shi[2][I_ * B_ * H_];        // s hi (fp16), dbl-buffered
__device__ __half g_Slo[2][I_ * B_ * H_];        // s residual (fp16)
__device__ float  g_C[2][I_ * B_ * H_];
__device__ unsigned g_count;
__device__ unsigned g_epoch;

__device__ __forceinline__ float sigf(float x) { return 1.0f / (1.0f + expf(-x)); }

__device__ __forceinline__ uint32_t smem_u32(const void* p) {
    uint32_t a;
    asm("{ .reg .u64 t; cvta.to.shared.u64 t, %1; cvt.u32.u64 %0, t; }" : "=r"(a) : "l"(p));
    return a;
}
__device__ __forceinline__ void cp16(uint32_t dst, const void* src, bool v) {
    int sz = v ? 16 : 0;
    asm volatile("cp.async.cg.shared.global [%0], [%1], 16, %2;"
                 :: "r"(dst), "l"(src), "r"(sz) : "memory");
}
#define CP_COMMIT() asm volatile("cp.async.commit_group;" ::: "memory")
#define CP_WAIT(n)  asm volatile("cp.async.wait_group %0;" :: "n"(n) : "memory")

__device__ __forceinline__ void ldmA(uint32_t* a, uint32_t addr) {
    asm volatile("ldmatrix.sync.aligned.m8n8.x4.shared.b16 {%0,%1,%2,%3}, [%4];"
                 : "=r"(a[0]), "=r"(a[1]), "=r"(a[2]), "=r"(a[3]) : "r"(addr));
}
__device__ __forceinline__ void ldmB(uint32_t* b, uint32_t addr) {
    asm volatile("ldmatrix.sync.aligned.m8n8.x2.shared.b16 {%0,%1}, [%2];"
                 : "=r"(b[0]), "=r"(b[1]) : "r"(addr));
}
__device__ __forceinline__ void mma16816(float* c, const uint32_t* a, const uint32_t* b) {
    asm volatile("mma.sync.aligned.m16n8k16.row.col.f32.f16.f16.f32 "
                 "{%0,%1,%2,%3}, {%4,%5,%6,%7}, {%8,%9}, {%0,%1,%2,%3};"
                 : "+f"(c[0]), "+f"(c[1]), "+f"(c[2]), "+f"(c[3])
                 : "r"(a[0]), "r"(a[1]), "r"(a[2]), "r"(a[3]), "r"(b[0]), "r"(b[1]));
}

// ---------------- grid barrier (monotonic epoch) -----------------------------
__device__ __forceinline__ unsigned ld_epoch() {
    unsigned e;
    asm volatile("ld.acquire.gpu.global.u32 %0, [%1];" : "=r"(e) : "l"(&g_epoch));
    return e;
}
__device__ __forceinline__ void grid_barrier(unsigned target) {
    __threadfence();
    __syncthreads();
    if (threadIdx.x == 0) {
        unsigned old;
        asm volatile("atom.add.release.gpu.global.u32 %0, [%1], 1;"
                     : "=r"(old) : "l"(&g_count) : "memory");
        if (old == NCTA - 1) {
            g_count = 0;
            asm volatile("red.release.gpu.global.add.u32 [%0], 1;"
                         :: "l"(&g_epoch) : "memory");
        } else {
            while ((int)(ld_epoch() - target) < 0) { }
        }
    }
    __syncthreads();
}

// ---------------------------------------------------------------------------
// Setup: W' fp16, h-major columns: W'[n'=h*5+g][k] = fp16(Ws[k][g*256+h])
// ---------------------------------------------------------------------------
__global__ __launch_bounds__(256) void split_ws_kernel(const float* __restrict__ Ws) {
    int idx = blockIdx.x * 256 + threadIdx.x;
    if (idx >= FIVEH * 512) return;
    int np = idx >> 9, k = idx & 511;
    int h = np / 5, g = np % 5;
    g_Wh[idx] = __float2half(Ws[k * FIVEH + g * H_ + h]);
}

// ---------------------------------------------------------------------------
// Precompute: PX = x@Wx_top, PY = y@Wx_bot (fp32 SIMT, gate-major cols)
// ---------------------------------------------------------------------------
__global__ __launch_bounds__(256) void precompute_kernel(
    const float* __restrict__ x, const float* __restrict__ y,
    const float* __restrict__ Wx)
{
    const int cell = blockIdx.x, n0 = blockIdx.y * 128, which = blockIdx.z;
    const float* A = which ? y : x;
    const int koff = which ? F_ : 0;
    float* P = which ? g_PY : g_PX;

    __shared__ float As[16][68];
    __shared__ float Bs[16][128];
    const int t = threadIdx.x;
    const int tx = t & 15, ty = t >> 4;
    const int lm = t >> 2, lk = (t & 3) * 4;

    float acc[4][8];
#pragma unroll
    for (int r = 0; r < 4; r++)
#pragma unroll
        for (int q = 0; q < 8; q++) acc[r][q] = 0.f;

    for (int k0 = 0; k0 < F_; k0 += 16) {
        float4 av = *(const float4*)&A[(lm * I_ + cell) * F_ + k0 + lk];
        As[lk + 0][lm] = av.x; As[lk + 1][lm] = av.y;
        As[lk + 2][lm] = av.z; As[lk + 3][lm] = av.w;
#pragma unroll
        for (int s = 0; s < 2; s++) {
            int idx = t + 256 * s;
            int kl = idx >> 5, c4 = idx & 31;
            *(float4*)&Bs[kl][c4 * 4] =
                *(const float4*)&Wx[(koff + k0 + kl) * FIVEH + n0 + c4 * 4];
        }
        __syncthreads();
#pragma unroll
        for (int k = 0; k < 16; k++) {
            float4 a4 = *(const float4*)&As[k][ty * 4];
            float4 b0 = *(const float4*)&Bs[k][tx * 8];
            float4 b1 = *(const float4*)&Bs[k][tx * 8 + 4];
            float a[4] = {a4.x, a4.y, a4.z, a4.w};
            float bb[8] = {b0.x, b0.y, b0.z, b0.w, b1.x, b1.y, b1.z, b1.w};
#pragma unroll
            for (int r = 0; r < 4; r++)
#pragma unroll
                for (int q = 0; q < 8; q++) acc[r][q] += a[r] * bb[q];
        }
        __syncthreads();
    }
#pragma unroll
    for (int r = 0; r < 4; r++) {
        int m = ty * 4 + r;
        float* dst = &P[(cell * B_ + m) * FIVEH + n0 + tx * 8];
        *(float4*)dst       = make_float4(acc[r][0], acc[r][1], acc[r][2], acc[r][3]);
        *(float4*)(dst + 4) = make_float4(acc[r][4], acc[r][5], acc[r][6], acc[r][7]);
    }
}

// ---------------------------------------------------------------------------
// Fused tile: one cell (M=64 batches) x 32-h slice (N=160 = 32h x 5 gates),
// K=1024 virtual: [s_hi(512); s_lo(512)] @ W_hi — B loaded once per k-chunk.
// GEMM epilogue does the full 2D-LSTM gate math and writes states + out.
// ---------------------------------------------------------------------------
__device__ __forceinline__ void fused_tile(
    char* smem, uint32_t sb,
    const float* __restrict__ bias, float* __restrict__ out,
    int d, int i, int htile)
{
    const int t = threadIdx.x, wid = t >> 5, lane = t & 31;
    const int j = d - i;
    const int prv = (d & 1) ^ 1, cur = d & 1;
    const bool hh = (i > 0), vv = (j > 0);
    const int n_base = htile * 160;      // n' offset into W'

    const __half* __restrict__ Shp = g_Shi[prv];
    const __half* __restrict__ Slp = g_Slo[prv];

    __syncthreads();   // protect smem reuse across tasks

    // ---- superchunk loader: B k-cols [sc*64, +64) + A hi/lo ----
    auto load_super = [&](int sc, int buf) {
        const uint32_t base = sb + buf * STAGE;
        const bool hor = (sc < 4);
        const int kc = (sc & 3) * 64;
        const int scell = hor ? (hh ? i - 1 : 0) : i;
        const bool valid = hor ? hh : vv;
        const int kb = sc * 64;
        // B: 160 rows x 64 k fp16
#pragma unroll
        for (int p = 0; p < 5; p++) {
            int idx = t + 256 * p;
            int r = idx >> 3, seg = idx & 7;
            cp16(base + r * 144 + seg * 16,
                 g_Wh + (size_t)(n_base + r) * 512 + kb + seg * 8, true);
        }
        // A hi then lo: 64 rows x 64 k each
#pragma unroll
        for (int pass = 0; pass < 2; pass++) {
            const __half* S = pass ? Slp : Shp;
#pragma unroll
            for (int p = 0; p < 2; p++) {
                int idx = t + 256 * p;
                int b = idx >> 3, seg = idx & 7;
                cp16(base + BBYTES + pass * APASS + b * 144 + seg * 16,
                     S + ((size_t)scell * B_ + b) * H_ + kc + seg * 8, valid);
            }
        }
    };

    // warp tiling: 2m x 4n; warp tile m32 x n40
    const int wm = wid & 1, wn = wid >> 1;
    const int m0 = wm * 32, n0 = wn * 40;
    const uint32_t arow = (uint32_t)((m0 + ((lane >> 3) & 1) * 8 + (lane & 7)) * 144
                                     + (lane >> 4) * 16);
    const uint32_t brow = (uint32_t)((n0 + (lane & 7)) * 144 + ((lane >> 3) & 1) * 16);

    float acc[2][5][4];
#pragma unroll
    for (int f = 0; f < 2; f++)
#pragma unroll
        for (int e = 0; e < 5; e++)
#pragma unroll
            for (int q = 0; q < 4; q++) acc[f][e][q] = 0.f;

    load_super(0, 0);
    CP_COMMIT();

    for (int sc = 0; sc < 8; sc++) {
        if (sc < 7) {
            load_super(sc + 1, (sc + 1) & 1);
            CP_COMMIT();
            CP_WAIT(1);
        } else {
            CP_WAIT(0);
        }
        __syncthreads();

        const uint32_t base = sb + (sc & 1) * STAGE;
#pragma unroll
        for (int ks = 0; ks < 4; ks++) {
            uint32_t bfr[5][2];
#pragma unroll
            for (int e = 0; e < 5; e++)
                ldmB(bfr[e], base + brow + e * 1152 + ks * 32);
#pragma unroll
            for (int pass = 0; pass < 2; pass++) {
                uint32_t afr[2][4];
#pragma unroll
                for (int f = 0; f < 2; f++)
                    ldmA(afr[f], base + BBYTES + pass * APASS + arow
                                 + f * 2304 + ks * 32);
#pragma unroll
                for (int f = 0; f < 2; f++)
#pragma unroll
                    for (int e = 0; e < 5; e++)
                        mma16816(acc[f][e], afr[f], bfr[e]);
            }
        }
        if (sc < 7) __syncthreads();
    }

    // ---- epilogue: acc -> smem pre [64 rows][160 n'] ----
    __syncthreads();
    float* pre = (float*)smem;
#pragma unroll
    for (int f = 0; f < 2; f++) {
#pragma unroll
        for (int e = 0; e < 5; e++) {
            int row = m0 + f * 16 + (lane >> 2);
            int col = n0 + e * 8 + (lane & 3) * 2;
            *(float2*)&pre[row * 160 + col]       = make_float2(acc[f][e][0], acc[f][e][1]);
            *(float2*)&pre[(row + 8) * 160 + col] = make_float2(acc[f][e][2], acc[f][e][3]);
        }
    }
    __syncthreads();

    // ---- gate math: 2048 items = 64 b x 32 h ----
    const float* __restrict__ Cp = g_C[prv];
    float* __restrict__ Cc = g_C[cur];
    __half* __restrict__ Shc = g_Shi[cur];
    __half* __restrict__ Slc = g_Slo[cur];

#pragma unroll
    for (int p = 0; p < 8; p++) {
        const int id = t + 256 * p;
        const int b = id >> 5, hl = id & 31;
        const int h = htile * 32 + hl;

        const float* PXr = g_PX + ((size_t)i * B_ + b) * FIVEH;
        const float* PYr = g_PY + ((size_t)j * B_ + b) * FIVEH;

        float pg[5];
#pragma unroll
        for (int g = 0; g < 5; g++) {
            const int col = g * H_ + h;
            pg[g] = pre[b * 160 + hl * 5 + g] + PXr[col] + PYr[col] + bias[col];
        }
        float ch = hh ? Cp[(((i - 1) * B_) + b) * H_ + h] : 0.f;
        float cv = vv ? Cp[((i * B_) + b) * H_ + h] : 0.f;

        float ig = sigf(pg[0]);
        float fg = sigf(pg[1]);
        float og = sigf(pg[2]);
        float lg = sigf(pg[3]);
        float gg = tanhf(pg[4]);
        float c = fg * (lg * ch + (1.f - lg) * cv) + ig * gg;
        float s = og * tanhf(c);

        const size_t sidx = ((size_t)i * B_ + b) * H_ + h;
        Cc[sidx] = c;
        __half shi = __float2half(s);
        Shc[sidx] = shi;
        Slc[sidx] = __float2half(s - __half2float(shi));
        out[(((size_t)i * O_ + j) * B_ + b) * H_ + h] = s;
    }
}

// ---------------------------------------------------------------------------
// Persistent kernel: 95 diagonals, fused tiles, ONE barrier per diagonal
// ---------------------------------------------------------------------------
__global__ __launch_bounds__(256, 1) void persist_kernel(
    const float* __restrict__ bias, float* __restrict__ out)
{
    extern __shared__ char smem[];
    const uint32_t sb = smem_u32(smem);

    const unsigned epoch0 = ld_epoch();
    unsigned bars = 0;

    for (int d = 0; d < I_ + O_ - 1; d++) {
        const int i_lo = (d > O_ - 1) ? d - (O_ - 1) : 0;
        const int i_hi = (d < I_ - 1) ? d : I_ - 1;
        const int nv = i_hi - i_lo + 1;

        const int ntasks = nv * 8;
        for (int task = blockIdx.x; task < ntasks; task += NCTA) {
            const int q = task >> 3;        // cell on diagonal
            const int htile = task & 7;     // 32-h slice
            fused_tile(smem, sb, bias, out, d, i_lo + q, htile);
        }
        bars++; grid_barrier(epoch0 + bars);
    }
}

// ---------------------------------------------------------------------------
extern "C" void kernel_launch(void* const* d_in, const int* in_sizes, int n_in,
                              void* d_out, int out_size)
{
    const float* x  = (const float*)d_in[0];
    const float* y  = (const float*)d_in[1];
    const float* Wx = (const float*)d_in[2];
    const float* Ws = (const float*)d_in[3];
    const float* b  = (const float*)d_in[4];
    float* out = (float*)d_out;

    cudaFuncSetAttribute(persist_kernel, cudaFuncAttributeMaxDynamicSharedMemorySize,
                         SMEM_TOTAL);

    split_ws_kernel<<<(FIVEH * 512 + 255) / 256, 256>>>(Ws);
    precompute_kernel<<<dim3(I_, FIVEH / 128, 2), 256>>>(x, y, Wx);
    persist_kernel<<<NCTA, 256, SMEM_TOTAL>>>(b, out);
}